// round 1
// baseline (speedup 1.0000x reference)
#include <cuda_runtime.h>
#include <cuda_bf16.h>
#include <stdint.h>

#define DEV_INLINE __device__ __forceinline__

constexpr int BB = 8, S = 2048, DM = 768, DH = 64;   // batch, seq, model, head
constexpr int BSROWS = BB * S;                        // 16384

// ---------------- scratch (device globals; no allocs allowed) ----------------
__device__ __nv_bfloat16 g_Q[BSROWS * DH];
__device__ __nv_bfloat16 g_K[BSROWS * DH];
__device__ __nv_bfloat16 g_V[BSROWS * DH];
__device__ __nv_bfloat16 g_Wt[3 * DH * DM];   // [which][dv][k] transposed bf16 weights
__device__ float g_A[BSROWS * DH];            // softmax(scores)@V, fp32
__device__ float g_part[BB * 16 * DM];        // partial x2 row-sums
__device__ float g_xsum[BB * DM];
__device__ float g_c[BB * DH];                // exact column-sum of V per batch

// ---------------- helpers ----------------
DEV_INLINE void mma16816(float* d, const uint32_t* a, const uint32_t* b) {
    asm volatile(
        "mma.sync.aligned.m16n8k16.row.col.f32.bf16.bf16.f32 "
        "{%0,%1,%2,%3}, {%4,%5,%6,%7}, {%8,%9}, {%0,%1,%2,%3};\n"
        : "+f"(d[0]), "+f"(d[1]), "+f"(d[2]), "+f"(d[3])
        : "r"(a[0]), "r"(a[1]), "r"(a[2]), "r"(a[3]), "r"(b[0]), "r"(b[1]));
}

DEV_INLINE float ex2f(float x) { float y; asm("ex2.approx.f32 %0, %1;" : "=f"(y) : "f"(x)); return y; }

DEV_INLINE uint32_t packbf2(float a, float b) {
    __nv_bfloat162 h = __floats2bfloat162_rn(a, b);   // low = a, high = b
    return *reinterpret_cast<uint32_t*>(&h);
}

constexpr float L2E = 1.4426950408889634f;

// ---------------- kernel 1: transpose weights to bf16 [dv][k] ----------------
__global__ void prep_wt_kernel(const float* __restrict__ Wq,
                               const float* __restrict__ Wk,
                               const float* __restrict__ Wv) {
    int i = blockIdx.x * blockDim.x + threadIdx.x;
    if (i >= 3 * DH * DM) return;
    int which = i / (DH * DM);
    int r = i % (DH * DM);
    int dv = r / DM, k = r % DM;
    const float* W = (which == 0) ? Wq : (which == 1) ? Wk : Wv;
    g_Wt[i] = __float2bfloat16(W[k * DH + dv]);
}

// ---------------- kernel 2: projection GEMM: [16384,768]x[768,64] -> bf16 ----
// which: 0->g_Q (scaled 1/8), 1->g_K, 2->g_V
__global__ __launch_bounds__(256) void proj_kernel(const float* __restrict__ X,
                                                   int which,
                                                   const float* __restrict__ bias,
                                                   float scale) {
    __shared__ __nv_bfloat16 Xs[128][72];
    __shared__ __nv_bfloat16 Ws[64][72];
    const int tid = threadIdx.x;
    const int w = tid >> 5, l = tid & 31, g = l >> 2, t4 = l & 3;
    const int rowbase = blockIdx.x * 128;
    const __nv_bfloat16* Wt = g_Wt + which * (DH * DM);
    __nv_bfloat16* Out = (which == 0) ? g_Q : (which == 1) ? g_K : g_V;

    float acc[8][4];
#pragma unroll
    for (int nt = 0; nt < 8; nt++)
#pragma unroll
        for (int j = 0; j < 4; j++) acc[nt][j] = 0.f;

    for (int kc = 0; kc < 12; kc++) {
        if (kc) __syncthreads();
        // load X tile 128x64 fp32 -> bf16 smem
#pragma unroll
        for (int i = 0; i < 8; i++) {
            int e = tid + i * 256;            // 2048 float4
            int row = e >> 4, c4 = e & 15;
            float4 v = *(const float4*)(X + (size_t)(rowbase + row) * DM + kc * 64 + c4 * 4);
            *(__nv_bfloat162*)&Xs[row][c4 * 4]     = __floats2bfloat162_rn(v.x, v.y);
            *(__nv_bfloat162*)&Xs[row][c4 * 4 + 2] = __floats2bfloat162_rn(v.z, v.w);
        }
        // load W tile (already transposed bf16): rows dv, cols k-chunk
#pragma unroll
        for (int i = 0; i < 2; i++) {
            int e = tid + i * 256;            // 512 uint4
            int row = e >> 3, c8 = e & 7;
            *(uint4*)&Ws[row][c8 * 8] = *(const uint4*)(Wt + (size_t)row * DM + kc * 64 + c8 * 8);
        }
        __syncthreads();

        uint32_t a[4][4];
#pragma unroll
        for (int kt = 0; kt < 4; kt++) {
            int r0 = w * 16 + g, c0 = kt * 16 + 2 * t4;
            a[kt][0] = *(const uint32_t*)&Xs[r0][c0];
            a[kt][1] = *(const uint32_t*)&Xs[r0 + 8][c0];
            a[kt][2] = *(const uint32_t*)&Xs[r0][c0 + 8];
            a[kt][3] = *(const uint32_t*)&Xs[r0 + 8][c0 + 8];
        }
#pragma unroll
        for (int nt = 0; nt < 8; nt++) {
#pragma unroll
            for (int kt = 0; kt < 4; kt++) {
                uint32_t bfr[2];
                int rn = nt * 8 + g, ck = kt * 16 + 2 * t4;
                bfr[0] = *(const uint32_t*)&Ws[rn][ck];
                bfr[1] = *(const uint32_t*)&Ws[rn][ck + 8];
                mma16816(acc[nt], a[kt], bfr);
            }
        }
    }
    // epilogue: +bias, *scale, -> bf16
    const int r0 = rowbase + w * 16 + g;
#pragma unroll
    for (int nt = 0; nt < 8; nt++) {
        int c = nt * 8 + 2 * t4;
        float b0 = bias[c], b1 = bias[c + 1];
        uint32_t v0 = packbf2((acc[nt][0] + b0) * scale, (acc[nt][1] + b1) * scale);
        uint32_t v1 = packbf2((acc[nt][2] + b0) * scale, (acc[nt][3] + b1) * scale);
        *(uint32_t*)(Out + (size_t)r0 * DH + c) = v0;
        *(uint32_t*)(Out + (size_t)(r0 + 8) * DH + c) = v1;
    }
}

// ---------------- kernels 3/4/5: exact fp32 c = (sum_s x2) @ Wv + S*bv -------
__global__ void xsum_part_kernel(const float* __restrict__ x2) {
    int chunk = blockIdx.x;   // 0..15
    int b = blockIdx.y;       // 0..7
    const float* base = x2 + ((size_t)b * S + chunk * 128) * DM;
    for (int col = threadIdx.x; col < DM; col += 256) {
        float acc = 0.f;
#pragma unroll 4
        for (int s = 0; s < 128; s++) acc += base[(size_t)s * DM + col];
        g_part[(b * 16 + chunk) * DM + col] = acc;
    }
}

__global__ void xsum_combine_kernel() {
    int i = blockIdx.x * 256 + threadIdx.x;   // over 8*768
    if (i >= BB * DM) return;
    float acc = 0.f;
    int b = i / DM, col = i % DM;
#pragma unroll
    for (int p = 0; p < 16; p++) acc += g_part[(b * 16 + p) * DM + col];
    g_xsum[i] = acc;
}

__global__ void compute_c_kernel(const float* __restrict__ Wv, const float* __restrict__ bv) {
    int t = threadIdx.x;          // 512 threads: (b, d)
    int b = t >> 6, d = t & 63;
    const float* xs = g_xsum + b * DM;
    float acc = 0.f;
#pragma unroll 8
    for (int j = 0; j < DM; j++) acc += xs[j] * Wv[j * DH + d];
    g_c[t] = acc + 2048.0f * bv[d];
}

// ---------------- kernel 6: flash attention A = softmax(QK^T)@V --------------
__global__ __launch_bounds__(256) void attn_kernel() {
    __shared__ __nv_bfloat16 Qs[128][72];
    __shared__ __nv_bfloat16 Ks[64][72];
    __shared__ __nv_bfloat16 Vs[64][72];   // transposed: Vs[d][s]

    const int qt = blockIdx.x;   // 0..15
    const int b  = blockIdx.y;   // 0..7
    const int tid = threadIdx.x;
    const int w = tid >> 5, l = tid & 31, g = l >> 2, t4 = l & 3;

    const __nv_bfloat16* Qp = g_Q + ((size_t)b * S + qt * 128) * DH;
#pragma unroll
    for (int i = 0; i < 4; i++) {
        int e = tid + i * 256;   // 1024 uint4
        int row = e >> 3, c8 = e & 7;
        *(uint4*)&Qs[row][c8 * 8] = *(const uint4*)(Qp + (size_t)row * DH + c8 * 8);
    }
    __syncthreads();

    uint32_t aq[4][4];
#pragma unroll
    for (int kt = 0; kt < 4; kt++) {
        int r0 = w * 16 + g, c0 = kt * 16 + 2 * t4;
        aq[kt][0] = *(const uint32_t*)&Qs[r0][c0];
        aq[kt][1] = *(const uint32_t*)&Qs[r0 + 8][c0];
        aq[kt][2] = *(const uint32_t*)&Qs[r0][c0 + 8];
        aq[kt][3] = *(const uint32_t*)&Qs[r0 + 8][c0 + 8];
    }

    float o[8][4];
#pragma unroll
    for (int nv = 0; nv < 8; nv++)
#pragma unroll
        for (int j = 0; j < 4; j++) o[nv][j] = 0.f;
    float mrow[2] = {-1e30f, -1e30f};
    float lsum[2] = {0.f, 0.f};

    for (int ks = 0; ks < 32; ks++) {        // 32 steps of 64 keys
        __syncthreads();
        const __nv_bfloat16* Kp = g_K + ((size_t)b * S + ks * 64) * DH;
        const __nv_bfloat16* Vp = g_V + ((size_t)b * S + ks * 64) * DH;
#pragma unroll
        for (int i = 0; i < 2; i++) {        // K tile 64x64: 512 uint4
            int e = tid + i * 256;
            int row = e >> 3, c8 = e & 7;
            *(uint4*)&Ks[row][c8 * 8] = *(const uint4*)(Kp + (size_t)row * DH + c8 * 8);
        }
#pragma unroll
        for (int i = 0; i < 8; i++) {        // V tile transposed, packed s-pairs
            int e = tid + i * 256;           // 2048 pairs
            int d = e & 63, s2 = e >> 6;     // s2: 0..31
            __nv_bfloat162 pv;
            pv.x = Vp[(size_t)(2 * s2) * DH + d];
            pv.y = Vp[(size_t)(2 * s2 + 1) * DH + d];
            *(__nv_bfloat162*)&Vs[d][2 * s2] = pv;
        }
        __syncthreads();

        // scores S[16 x 64] per warp (Q pre-scaled by 1/8)
        float sc[8][4];
#pragma unroll
        for (int nt = 0; nt < 8; nt++) {
#pragma unroll
            for (int j = 0; j < 4; j++) sc[nt][j] = 0.f;
#pragma unroll
            for (int kt = 0; kt < 4; kt++) {
                uint32_t bfr[2];
                int rn = nt * 8 + g, ck = kt * 16 + 2 * t4;
                bfr[0] = *(const uint32_t*)&Ks[rn][ck];
                bfr[1] = *(const uint32_t*)&Ks[rn][ck + 8];
                mma16816(sc[nt], aq[kt], bfr);
            }
        }
        // online softmax
        float mt0 = -1e30f, mt1 = -1e30f;
#pragma unroll
        for (int nt = 0; nt < 8; nt++) {
            mt0 = fmaxf(mt0, fmaxf(sc[nt][0], sc[nt][1]));
            mt1 = fmaxf(mt1, fmaxf(sc[nt][2], sc[nt][3]));
        }
        mt0 = fmaxf(mt0, __shfl_xor_sync(0xffffffffu, mt0, 1));
        mt0 = fmaxf(mt0, __shfl_xor_sync(0xffffffffu, mt0, 2));
        mt1 = fmaxf(mt1, __shfl_xor_sync(0xffffffffu, mt1, 1));
        mt1 = fmaxf(mt1, __shfl_xor_sync(0xffffffffu, mt1, 2));
        float mn0 = fmaxf(mrow[0], mt0), mn1 = fmaxf(mrow[1], mt1);
        float corr0 = ex2f((mrow[0] - mn0) * L2E);
        float corr1 = ex2f((mrow[1] - mn1) * L2E);
        mrow[0] = mn0; mrow[1] = mn1;

        float rs0 = 0.f, rs1 = 0.f;
        uint32_t pa[4][4];
#pragma unroll
        for (int k2 = 0; k2 < 4; k2++) {
            float p00 = ex2f((sc[2 * k2][0] - mn0) * L2E);
            float p01 = ex2f((sc[2 * k2][1] - mn0) * L2E);
            float p10 = ex2f((sc[2 * k2][2] - mn1) * L2E);
            float p11 = ex2f((sc[2 * k2][3] - mn1) * L2E);
            float p20 = ex2f((sc[2 * k2 + 1][0] - mn0) * L2E);
            float p21 = ex2f((sc[2 * k2 + 1][1] - mn0) * L2E);
            float p30 = ex2f((sc[2 * k2 + 1][2] - mn1) * L2E);
            float p31 = ex2f((sc[2 * k2 + 1][3] - mn1) * L2E);
            rs0 += p00 + p01 + p20 + p21;
            rs1 += p10 + p11 + p30 + p31;
            pa[k2][0] = packbf2(p00, p01);
            pa[k2][1] = packbf2(p10, p11);
            pa[k2][2] = packbf2(p20, p21);
            pa[k2][3] = packbf2(p30, p31);
        }
        rs0 += __shfl_xor_sync(0xffffffffu, rs0, 1);
        rs0 += __shfl_xor_sync(0xffffffffu, rs0, 2);
        rs1 += __shfl_xor_sync(0xffffffffu, rs1, 1);
        rs1 += __shfl_xor_sync(0xffffffffu, rs1, 2);
        lsum[0] = lsum[0] * corr0 + rs0;
        lsum[1] = lsum[1] * corr1 + rs1;

#pragma unroll
        for (int nv = 0; nv < 8; nv++) {
            o[nv][0] *= corr0; o[nv][1] *= corr0;
            o[nv][2] *= corr1; o[nv][3] *= corr1;
        }
        // O += P @ V
#pragma unroll
        for (int nv = 0; nv < 8; nv++) {
#pragma unroll
            for (int k2 = 0; k2 < 4; k2++) {
                uint32_t bfr[2];
                int rd = nv * 8 + g, cs = k2 * 16 + 2 * t4;
                bfr[0] = *(const uint32_t*)&Vs[rd][cs];
                bfr[1] = *(const uint32_t*)&Vs[rd][cs + 8];
                mma16816(o[nv], pa[k2], bfr);
            }
        }
    }

    const float inv0 = 1.f / lsum[0];
    const float inv1 = 1.f / lsum[1];
    const int r0 = b * S + qt * 128 + w * 16 + g;
#pragma unroll
    for (int nv = 0; nv < 8; nv++) {
        int c = nv * 8 + 2 * t4;
        *(float2*)(g_A + (size_t)r0 * DH + c) = make_float2(o[nv][0] * inv0, o[nv][1] * inv0);
        *(float2*)(g_A + (size_t)(r0 + 8) * DH + c) = make_float2(o[nv][2] * inv1, o[nv][3] * inv1);
    }
}

// ---------------- kernel 7: out = LN((c - A)/2047) * gamma + beta ------------
__global__ __launch_bounds__(256) void ln_kernel(const float* __restrict__ gamma,
                                                 const float* __restrict__ beta,
                                                 float* __restrict__ out) {
    const int row = blockIdx.x * 8 + (threadIdx.x >> 5);
    const int l = threadIdx.x & 31;
    const int b = row >> 11;
    const float inv = 1.0f / 2047.0f;
    float v0 = (g_c[b * 64 + l]      - g_A[(size_t)row * 64 + l])      * inv;
    float v1 = (g_c[b * 64 + l + 32] - g_A[(size_t)row * 64 + l + 32]) * inv;
    float s1 = v0 + v1, s2 = v0 * v0 + v1 * v1;
#pragma unroll
    for (int off = 16; off; off >>= 1) {
        s1 += __shfl_xor_sync(0xffffffffu, s1, off);
        s2 += __shfl_xor_sync(0xffffffffu, s2, off);
    }
    float mu = s1 * (1.f / 64.f);
    float var = s2 * (1.f / 64.f) - mu * mu;
    float r = rsqrtf(var + 1e-5f);
    out[(size_t)row * 64 + l]      = (v0 - mu) * r * gamma[l] + beta[l];
    out[(size_t)row * 64 + l + 32] = (v1 - mu) * r * gamma[l + 32] + beta[l + 32];
}

// ---------------- launch ----------------
extern "C" void kernel_launch(void* const* d_in, const int* in_sizes, int n_in,
                              void* d_out, int out_size) {
    const float* x1 = (const float*)d_in[0];
    const float* x2 = (const float*)d_in[1];
    const float* Wq = (const float*)d_in[2];
    const float* bq = (const float*)d_in[3];
    const float* Wk = (const float*)d_in[4];
    const float* bk = (const float*)d_in[5];
    const float* Wv = (const float*)d_in[6];
    const float* bv = (const float*)d_in[7];
    const float* gamma = (const float*)d_in[8];
    const float* beta  = (const float*)d_in[9];
    float* out = (float*)d_out;

    prep_wt_kernel<<<(3 * DH * DM + 255) / 256, 256>>>(Wq, Wk, Wv);
    proj_kernel<<<BSROWS / 128, 256>>>(x1, 0, bq, 0.125f);   // Q pre-scaled 1/sqrt(64)
    proj_kernel<<<BSROWS / 128, 256>>>(x2, 1, bk, 1.0f);
    proj_kernel<<<BSROWS / 128, 256>>>(x2, 2, bv, 1.0f);
    xsum_part_kernel<<<dim3(16, BB), 256>>>(x2);
    xsum_combine_kernel<<<(BB * DM + 255) / 256, 256>>>();
    compute_c_kernel<<<1, 512>>>(Wv, bv);
    attn_kernel<<<dim3(16, BB), 256>>>();
    ln_kernel<<<BSROWS / 8, 256>>>(gamma, beta, out);
}

// round 2
// speedup vs baseline: 3.0291x; 3.0291x over previous
#include <cuda_runtime.h>
#include <cuda_bf16.h>
#include <stdint.h>

#define DEV_INLINE __device__ __forceinline__

constexpr int BB = 8, S = 2048, DM = 768, DH = 64;
constexpr int BSROWS = BB * S;                        // 16384

// ---------------- scratch ----------------
__device__ __nv_bfloat16 g_Q[BSROWS * DH];
__device__ __nv_bfloat16 g_K[BSROWS * DH];
__device__ __nv_bfloat16 g_Vt[BB * DH * S];          // transposed V: [b][d][s]
__device__ __nv_bfloat16 g_Wt[3 * DH * DM];          // [which][dv][k]
__device__ float g_part4[128 * 4 * DM];              // per-KV-block x2 col partials
__device__ float g_xsum[BB * DM];
__device__ float g_c[BB * DH];

// ---------------- helpers ----------------
DEV_INLINE void mma16816(float* d, const uint32_t* a, const uint32_t* b) {
    asm volatile(
        "mma.sync.aligned.m16n8k16.row.col.f32.bf16.bf16.f32 "
        "{%0,%1,%2,%3}, {%4,%5,%6,%7}, {%8,%9}, {%0,%1,%2,%3};\n"
        : "+f"(d[0]), "+f"(d[1]), "+f"(d[2]), "+f"(d[3])
        : "r"(a[0]), "r"(a[1]), "r"(a[2]), "r"(a[3]), "r"(b[0]), "r"(b[1]));
}
DEV_INLINE float ex2f(float x) { float y; asm("ex2.approx.f32 %0, %1;" : "=f"(y) : "f"(x)); return y; }
DEV_INLINE uint32_t packbf2(float a, float b) {
    __nv_bfloat162 h = __floats2bfloat162_rn(a, b);
    return *reinterpret_cast<uint32_t*>(&h);
}
DEV_INLINE void cp_async16(void* smem, const void* gmem) {
    uint32_t s = (uint32_t)__cvta_generic_to_shared(smem);
    asm volatile("cp.async.cg.shared.global [%0], [%1], 16;\n" :: "r"(s), "l"(gmem));
}
DEV_INLINE void cp_commit() { asm volatile("cp.async.commit_group;\n"); }
template<int N> DEV_INLINE void cp_wait() { asm volatile("cp.async.wait_group %0;\n" :: "n"(N)); }

constexpr float L2E = 1.4426950408889634f;

// ---------------- kernel 1: transpose weights to bf16 [dv][k] ----------------
__global__ void prep_wt_kernel(const float* __restrict__ Wq,
                               const float* __restrict__ Wk,
                               const float* __restrict__ Wv) {
    int i = blockIdx.x * blockDim.x + threadIdx.x;
    if (i >= 3 * DH * DM) return;
    int which = i / (DH * DM);
    int r = i % (DH * DM);
    int dv = r / DM, k = r % DM;
    const float* W = (which == 0) ? Wq : (which == 1) ? Wk : Wv;
    g_Wt[i] = __float2bfloat16(W[k * DH + dv]);
}

// ---------------- kernel 2: pipelined projection GEMM ----------------
// NT=8: Q (width 64, X=x1, scale=1/8). NT=16: K|V fused (width 128, X=x2),
// also emits x2 column-sum partials and V transposed.
template<int NT>
__global__ __launch_bounds__(256) void proj_kernel(
    const float* __restrict__ X, int woff,
    const float* __restrict__ bias0, const float* __restrict__ bias1,
    float scale, int do_xsum)
{
    extern __shared__ char smraw[];
    float (*Xs)[128][68] = (float(*)[128][68])smraw;                       // 2 stages fp32
    __nv_bfloat16 (*Ws)[NT * 8][72] =
        (__nv_bfloat16(*)[NT * 8][72])(smraw + 2 * 128 * 68 * 4);          // 2 stages bf16

    const int tid = threadIdx.x;
    const int w = tid >> 5, l = tid & 31, g = l >> 2, t4 = l & 3;
    const int rowbase = blockIdx.x * 128;
    const __nv_bfloat16* Wt = g_Wt + woff;

    float acc[NT][4];
#pragma unroll
    for (int nt = 0; nt < NT; nt++)
#pragma unroll
        for (int j = 0; j < 4; j++) acc[nt][j] = 0.f;

    // prologue: stage 0
    {
#pragma unroll
        for (int i = 0; i < 8; i++) {
            int e = tid + i * 256; int row = e >> 4, c4 = e & 15;
            cp_async16(&Xs[0][row][c4 * 4], X + (size_t)(rowbase + row) * DM + c4 * 4);
        }
#pragma unroll
        for (int i = 0; i < NT / 4; i++) {
            int e = tid + i * 256; int row = e >> 3, c8 = e & 7;
            cp_async16(&Ws[0][row][c8 * 8], Wt + (size_t)row * DM + c8 * 8);
        }
        cp_commit();
    }

    for (int kc = 0; kc < 12; kc++) {
        const int st = kc & 1;
        if (kc + 1 < 12) {
#pragma unroll
            for (int i = 0; i < 8; i++) {
                int e = tid + i * 256; int row = e >> 4, c4 = e & 15;
                cp_async16(&Xs[st ^ 1][row][c4 * 4],
                           X + (size_t)(rowbase + row) * DM + (kc + 1) * 64 + c4 * 4);
            }
#pragma unroll
            for (int i = 0; i < NT / 4; i++) {
                int e = tid + i * 256; int row = e >> 3, c8 = e & 7;
                cp_async16(&Ws[st ^ 1][row][c8 * 8],
                           Wt + (size_t)row * DM + (kc + 1) * 64 + c8 * 8);
            }
            cp_commit();
            cp_wait<1>();
        } else {
            cp_wait<0>();
        }
        __syncthreads();

        if (do_xsum) {   // exact fp32 column sums of this 128x64 tile
            const int q = tid >> 6, c = tid & 63;
            float s = 0.f;
#pragma unroll 8
            for (int r = 0; r < 32; r++) s += Xs[st][q * 32 + r][c];
            g_part4[((size_t)blockIdx.x * 4 + q) * DM + kc * 64 + c] = s;
        }

        uint32_t a[4][4];
#pragma unroll
        for (int kt = 0; kt < 4; kt++) {
            int r0 = w * 16 + g, c0 = kt * 16 + 2 * t4;
            a[kt][0] = packbf2(Xs[st][r0][c0],         Xs[st][r0][c0 + 1]);
            a[kt][1] = packbf2(Xs[st][r0 + 8][c0],     Xs[st][r0 + 8][c0 + 1]);
            a[kt][2] = packbf2(Xs[st][r0][c0 + 8],     Xs[st][r0][c0 + 9]);
            a[kt][3] = packbf2(Xs[st][r0 + 8][c0 + 8], Xs[st][r0 + 8][c0 + 9]);
        }
#pragma unroll
        for (int nt = 0; nt < NT; nt++) {
#pragma unroll
            for (int kt = 0; kt < 4; kt++) {
                uint32_t bfr[2];
                int rn = nt * 8 + g, ck = kt * 16 + 2 * t4;
                bfr[0] = *(const uint32_t*)&Ws[st][rn][ck];
                bfr[1] = *(const uint32_t*)&Ws[st][rn][ck + 8];
                mma16816(acc[nt], a[kt], bfr);
            }
        }
        __syncthreads();
    }

    const int r0 = rowbase + w * 16 + g;
    if (NT == 8) {
        // Q epilogue
#pragma unroll
        for (int nt = 0; nt < NT; nt++) {
            int c = nt * 8 + 2 * t4;
            float b0 = bias0[c], b1 = bias0[c + 1];
            *(uint32_t*)(g_Q + (size_t)r0 * DH + c) =
                packbf2((acc[nt][0] + b0) * scale, (acc[nt][1] + b1) * scale);
            *(uint32_t*)(g_Q + (size_t)(r0 + 8) * DH + c) =
                packbf2((acc[nt][2] + b0) * scale, (acc[nt][3] + b1) * scale);
        }
    } else {
        // K epilogue (cols 0..63)
#pragma unroll
        for (int nt = 0; nt < 8; nt++) {
            int c = nt * 8 + 2 * t4;
            float b0 = bias0[c], b1 = bias0[c + 1];
            *(uint32_t*)(g_K + (size_t)r0 * DH + c) =
                packbf2(acc[nt][0] + b0, acc[nt][1] + b1);
            *(uint32_t*)(g_K + (size_t)(r0 + 8) * DH + c) =
                packbf2(acc[nt][2] + b0, acc[nt][3] + b1);
        }
        // V: stage to smem [s][d], then transposed coalesced write to g_Vt
        __nv_bfloat16 (*Vsm)[72] = (__nv_bfloat16(*)[72])&Ws[0][0][0];
#pragma unroll
        for (int nt = 8; nt < 16; nt++) {
            int c = (nt - 8) * 8 + 2 * t4;
            float b0 = bias1[c], b1 = bias1[c + 1];
            *(uint32_t*)&Vsm[w * 16 + g][c]     = packbf2(acc[nt][0] + b0, acc[nt][1] + b1);
            *(uint32_t*)&Vsm[w * 16 + g + 8][c] = packbf2(acc[nt][2] + b0, acc[nt][3] + b1);
        }
        __syncthreads();
        const int b = rowbase >> 11, s0 = rowbase & 2047;
        const int d = tid >> 2, part = tid & 3;
#pragma unroll
        for (int jj = 0; jj < 4; jj++) {
            __nv_bfloat16 tmp[8];
#pragma unroll
            for (int m = 0; m < 8; m++) tmp[m] = Vsm[part * 32 + jj * 8 + m][d];
            *(uint4*)(g_Vt + ((size_t)(b * DH + d)) * S + s0 + part * 32 + jj * 8) =
                *(uint4*)tmp;
        }
    }
}

// ---------------- kernel 3: combine x2 partial sums ----------------
__global__ void xsum_combine_kernel() {
    int i = blockIdx.x * 256 + threadIdx.x;
    if (i >= BB * DM) return;
    int b = i / DM, c = i % DM;
    float a = 0.f;
#pragma unroll
    for (int blk = 0; blk < 16; blk++)
#pragma unroll
        for (int q = 0; q < 4; q++)
            a += g_part4[((size_t)(b * 16 + blk) * 4 + q) * DM + c];
    g_xsum[i] = a;
}

// ---------------- kernel 4: c = xsum @ Wv + S*bv (warp per output) ----------
__global__ void compute_c_kernel(const float* __restrict__ Wv, const float* __restrict__ bv) {
    int idx = blockIdx.x * 8 + (threadIdx.x >> 5);   // 0..511
    int lane = threadIdx.x & 31;
    int b = idx >> 6, d = idx & 63;
    const float* xs = g_xsum + b * DM;
    float acc = 0.f;
#pragma unroll
    for (int i = 0; i < DM / 32; i++) {
        int j = lane + i * 32;
        acc += xs[j] * Wv[j * DH + d];
    }
#pragma unroll
    for (int off = 16; off; off >>= 1) acc += __shfl_xor_sync(0xffffffffu, acc, off);
    if (lane == 0) g_c[idx] = acc + 2048.0f * bv[d];
}

// ---------------- kernel 5: flash attention + reverse-transform + LN --------
__global__ __launch_bounds__(256) void attn_kernel(const float* __restrict__ gamma,
                                                   const float* __restrict__ beta,
                                                   float* __restrict__ out) {
    __shared__ __align__(16) char sm[36864 + 768];
    __nv_bfloat16 (*Qs)[72]     = (__nv_bfloat16(*)[72])sm;                  // union w/ K,V
    __nv_bfloat16 (*Ks)[64][72] = (__nv_bfloat16(*)[64][72])sm;              // stages at 0, 9216
    __nv_bfloat16 (*Vs)[64][72] = (__nv_bfloat16(*)[64][72])(sm + 18432);    // stages at 18432, 27648
    float* cs = (float*)(sm + 36864);   // c[64] | gamma[64] | beta[64]

    const int qt = blockIdx.x;
    const int b  = blockIdx.y;
    const int tid = threadIdx.x;
    const int w = tid >> 5, l = tid & 31, g = l >> 2, t4 = l & 3;

    // Q tile via cp.async; c/gamma/beta via plain loads (disjoint smem region)
    const __nv_bfloat16* Qp = g_Q + ((size_t)b * S + qt * 128) * DH;
#pragma unroll
    for (int i = 0; i < 4; i++) {
        int e = tid + i * 256; int row = e >> 3, c8 = e & 7;
        cp_async16(&Qs[row][c8 * 8], Qp + (size_t)row * DH + c8 * 8);
    }
    cp_commit();
    if (tid < 64)        cs[tid]       = g_c[b * 64 + tid];
    else if (tid < 128)  cs[tid]       = gamma[tid - 64];
    else if (tid < 192)  cs[tid]       = beta[tid - 128];
    cp_wait<0>();
    __syncthreads();

    uint32_t aq[4][4];
#pragma unroll
    for (int kt = 0; kt < 4; kt++) {
        int r0 = w * 16 + g, c0 = kt * 16 + 2 * t4;
        aq[kt][0] = *(const uint32_t*)&Qs[r0][c0];
        aq[kt][1] = *(const uint32_t*)&Qs[r0 + 8][c0];
        aq[kt][2] = *(const uint32_t*)&Qs[r0][c0 + 8];
        aq[kt][3] = *(const uint32_t*)&Qs[r0 + 8][c0 + 8];
    }
    __syncthreads();   // Q region about to be overwritten by K stage 0

    const __nv_bfloat16* Kb  = g_K  + (size_t)b * S * DH;
    const __nv_bfloat16* Vtb = g_Vt + (size_t)b * DH * S;

    // prologue: K/V stage 0
    {
#pragma unroll
        for (int i = 0; i < 2; i++) {
            int e = tid + i * 256; int row = e >> 3, c8 = e & 7;
            cp_async16(&Ks[0][row][c8 * 8], Kb + (size_t)row * DH + c8 * 8);
        }
#pragma unroll
        for (int i = 0; i < 2; i++) {
            int e = tid + i * 256; int row = e >> 3, c8 = e & 7;
            cp_async16(&Vs[0][row][c8 * 8], Vtb + (size_t)row * S + c8 * 8);
        }
        cp_commit();
    }

    float o[8][4];
#pragma unroll
    for (int nv = 0; nv < 8; nv++)
#pragma unroll
        for (int j = 0; j < 4; j++) o[nv][j] = 0.f;
    float mrow[2] = {-1e30f, -1e30f};
    float lsum[2] = {0.f, 0.f};

    for (int ks = 0; ks < 32; ks++) {
        const int st = ks & 1;
        if (ks + 1 < 32) {
#pragma unroll
            for (int i = 0; i < 2; i++) {
                int e = tid + i * 256; int row = e >> 3, c8 = e & 7;
                cp_async16(&Ks[st ^ 1][row][c8 * 8],
                           Kb + (size_t)((ks + 1) * 64 + row) * DH + c8 * 8);
            }
#pragma unroll
            for (int i = 0; i < 2; i++) {
                int e = tid + i * 256; int row = e >> 3, c8 = e & 7;
                cp_async16(&Vs[st ^ 1][row][c8 * 8],
                           Vtb + (size_t)row * S + (ks + 1) * 64 + c8 * 8);
            }
            cp_commit();
            cp_wait<1>();
        } else {
            cp_wait<0>();
        }
        __syncthreads();

        float sc[8][4];
#pragma unroll
        for (int nt = 0; nt < 8; nt++) {
#pragma unroll
            for (int j = 0; j < 4; j++) sc[nt][j] = 0.f;
#pragma unroll
            for (int kt = 0; kt < 4; kt++) {
                uint32_t bfr[2];
                int rn = nt * 8 + g, ck = kt * 16 + 2 * t4;
                bfr[0] = *(const uint32_t*)&Ks[st][rn][ck];
                bfr[1] = *(const uint32_t*)&Ks[st][rn][ck + 8];
                mma16816(sc[nt], aq[kt], bfr);
            }
        }
        // online softmax
        float mt0 = -1e30f, mt1 = -1e30f;
#pragma unroll
        for (int nt = 0; nt < 8; nt++) {
            mt0 = fmaxf(mt0, fmaxf(sc[nt][0], sc[nt][1]));
            mt1 = fmaxf(mt1, fmaxf(sc[nt][2], sc[nt][3]));
        }
        mt0 = fmaxf(mt0, __shfl_xor_sync(0xffffffffu, mt0, 1));
        mt0 = fmaxf(mt0, __shfl_xor_sync(0xffffffffu, mt0, 2));
        mt1 = fmaxf(mt1, __shfl_xor_sync(0xffffffffu, mt1, 1));
        mt1 = fmaxf(mt1, __shfl_xor_sync(0xffffffffu, mt1, 2));
        float mn0 = fmaxf(mrow[0], mt0), mn1 = fmaxf(mrow[1], mt1);
        float corr0 = ex2f((mrow[0] - mn0) * L2E);
        float corr1 = ex2f((mrow[1] - mn1) * L2E);
        mrow[0] = mn0; mrow[1] = mn1;

        float rs0 = 0.f, rs1 = 0.f;
        uint32_t pa[4][4];
#pragma unroll
        for (int k2 = 0; k2 < 4; k2++) {
            float p00 = ex2f((sc[2 * k2][0] - mn0) * L2E);
            float p01 = ex2f((sc[2 * k2][1] - mn0) * L2E);
            float p10 = ex2f((sc[2 * k2][2] - mn1) * L2E);
            float p11 = ex2f((sc[2 * k2][3] - mn1) * L2E);
            float p20 = ex2f((sc[2 * k2 + 1][0] - mn0) * L2E);
            float p21 = ex2f((sc[2 * k2 + 1][1] - mn0) * L2E);
            float p30 = ex2f((sc[2 * k2 + 1][2] - mn1) * L2E);
            float p31 = ex2f((sc[2 * k2 + 1][3] - mn1) * L2E);
            rs0 += p00 + p01 + p20 + p21;
            rs1 += p10 + p11 + p30 + p31;
            pa[k2][0] = packbf2(p00, p01);
            pa[k2][1] = packbf2(p10, p11);
            pa[k2][2] = packbf2(p20, p21);
            pa[k2][3] = packbf2(p30, p31);
        }
        rs0 += __shfl_xor_sync(0xffffffffu, rs0, 1);
        rs0 += __shfl_xor_sync(0xffffffffu, rs0, 2);
        rs1 += __shfl_xor_sync(0xffffffffu, rs1, 1);
        rs1 += __shfl_xor_sync(0xffffffffu, rs1, 2);
        lsum[0] = lsum[0] * corr0 + rs0;
        lsum[1] = lsum[1] * corr1 + rs1;

#pragma unroll
        for (int nv = 0; nv < 8; nv++) {
            o[nv][0] *= corr0; o[nv][1] *= corr0;
            o[nv][2] *= corr1; o[nv][3] *= corr1;
        }
#pragma unroll
        for (int nv = 0; nv < 8; nv++) {
#pragma unroll
            for (int k2 = 0; k2 < 4; k2++) {
                uint32_t bfr[2];
                int rd = nv * 8 + g, cs2 = k2 * 16 + 2 * t4;
                bfr[0] = *(const uint32_t*)&Vs[st][rd][cs2];
                bfr[1] = *(const uint32_t*)&Vs[st][rd][cs2 + 8];
                mma16816(o[nv], pa[k2], bfr);
            }
        }
        __syncthreads();
    }

    // fused epilogue: v = (c - A)/2047, LayerNorm over 64 cols (quad-shuffle)
    const float inv0 = 1.f / lsum[0];
    const float inv1 = 1.f / lsum[1];
    const float isc = 1.f / 2047.f;
    float s1a = 0.f, s2a = 0.f, s1b = 0.f, s2b = 0.f;
#pragma unroll
    for (int nv = 0; nv < 8; nv++) {
        int c = nv * 8 + 2 * t4;
        float cc0 = cs[c], cc1 = cs[c + 1];
        float x0 = (cc0 - o[nv][0] * inv0) * isc;
        float x1 = (cc1 - o[nv][1] * inv0) * isc;
        float y0 = (cc0 - o[nv][2] * inv1) * isc;
        float y1 = (cc1 - o[nv][3] * inv1) * isc;
        s1a += x0 + x1; s2a += x0 * x0 + x1 * x1;
        s1b += y0 + y1; s2b += y0 * y0 + y1 * y1;
        o[nv][0] = x0; o[nv][1] = x1; o[nv][2] = y0; o[nv][3] = y1;
    }
#pragma unroll
    for (int off = 1; off <= 2; off <<= 1) {
        s1a += __shfl_xor_sync(0xffffffffu, s1a, off);
        s2a += __shfl_xor_sync(0xffffffffu, s2a, off);
        s1b += __shfl_xor_sync(0xffffffffu, s1b, off);
        s2b += __shfl_xor_sync(0xffffffffu, s2b, off);
    }
    float mu0 = s1a * (1.f / 64.f), var0 = s2a * (1.f / 64.f) - mu0 * mu0;
    float mu1 = s1b * (1.f / 64.f), var1 = s2b * (1.f / 64.f) - mu1 * mu1;
    float r0f = rsqrtf(var0 + 1e-5f);
    float r1f = rsqrtf(var1 + 1e-5f);

    const float* gs = cs + 64;
    const float* bs = cs + 128;
    const int row0 = b * S + qt * 128 + w * 16 + g;
#pragma unroll
    for (int nv = 0; nv < 8; nv++) {
        int c = nv * 8 + 2 * t4;
        float ga0 = gs[c], ga1 = gs[c + 1], be0 = bs[c], be1 = bs[c + 1];
        *(float2*)(out + (size_t)row0 * DH + c) =
            make_float2((o[nv][0] - mu0) * r0f * ga0 + be0,
                        (o[nv][1] - mu0) * r0f * ga1 + be1);
        *(float2*)(out + (size_t)(row0 + 8) * DH + c) =
            make_float2((o[nv][2] - mu1) * r1f * ga0 + be0,
                        (o[nv][3] - mu1) * r1f * ga1 + be1);
    }
}

// ---------------- launch ----------------
extern "C" void kernel_launch(void* const* d_in, const int* in_sizes, int n_in,
                              void* d_out, int out_size) {
    const float* x1 = (const float*)d_in[0];
    const float* x2 = (const float*)d_in[1];
    const float* Wq = (const float*)d_in[2];
    const float* bq = (const float*)d_in[3];
    const float* Wk = (const float*)d_in[4];
    const float* bk = (const float*)d_in[5];
    const float* Wv = (const float*)d_in[6];
    const float* bv = (const float*)d_in[7];
    const float* gamma = (const float*)d_in[8];
    const float* beta  = (const float*)d_in[9];
    float* out = (float*)d_out;

    const int SM8  = 2 * 128 * 68 * 4 + 2 * 64 * 72 * 2;    // 88064
    const int SM16 = 2 * 128 * 68 * 4 + 2 * 128 * 72 * 2;   // 106496
    cudaFuncSetAttribute(proj_kernel<8>,  cudaFuncAttributeMaxDynamicSharedMemorySize, SM8);
    cudaFuncSetAttribute(proj_kernel<16>, cudaFuncAttributeMaxDynamicSharedMemorySize, SM16);

    prep_wt_kernel<<<(3 * DH * DM + 255) / 256, 256>>>(Wq, Wk, Wv);
    proj_kernel<8><<<128, 256, SM8>>>(x1, 0, bq, bq, 0.125f, 0);
    proj_kernel<16><<<128, 256, SM16>>>(x2, DH * DM, bk, bv, 1.0f, 1);
    xsum_combine_kernel<<<(BB * DM + 255) / 256, 256>>>();
    compute_c_kernel<<<64, 256>>>(Wv, bv);
    attn_kernel<<<dim3(16, BB), 256>>>(gamma, beta, out);
}

// round 3
// speedup vs baseline: 3.6468x; 1.2039x over previous
#include <cuda_runtime.h>
#include <cuda_bf16.h>
#include <stdint.h>

#define DEV_INLINE __device__ __forceinline__

constexpr int BB = 8, S = 2048, DM = 768, DH = 64;
constexpr int BSROWS = BB * S;

// ---------------- scratch ----------------
__device__ __nv_bfloat16 g_Q[BSROWS * DH];
__device__ __nv_bfloat16 g_K[BSROWS * DH];
__device__ __nv_bfloat16 g_Vt[BB * DH * S];          // [b][d][s]
__device__ __nv_bfloat16 g_Wt[3 * DH * DM];          // [which][dv][k]
__device__ float g_WvtF[DH * DM];                    // fp32 Wv transposed [d][k]
__device__ float g_part4[128 * 4 * DM];
__device__ float g_xsum[BB * DM];
__device__ float g_c[BB * DH];

// ---------------- helpers ----------------
DEV_INLINE void mma16816(float* d, const uint32_t* a, const uint32_t* b) {
    asm volatile(
        "mma.sync.aligned.m16n8k16.row.col.f32.bf16.bf16.f32 "
        "{%0,%1,%2,%3}, {%4,%5,%6,%7}, {%8,%9}, {%0,%1,%2,%3};\n"
        : "+f"(d[0]), "+f"(d[1]), "+f"(d[2]), "+f"(d[3])
        : "r"(a[0]), "r"(a[1]), "r"(a[2]), "r"(a[3]), "r"(b[0]), "r"(b[1]));
}
DEV_INLINE float ex2f(float x) { float y; asm("ex2.approx.f32 %0, %1;" : "=f"(y) : "f"(x)); return y; }
DEV_INLINE uint32_t packbf2(float a, float b) {
    __nv_bfloat162 h = __floats2bfloat162_rn(a, b);
    return *reinterpret_cast<uint32_t*>(&h);
}
DEV_INLINE void cp_async16(void* smem, const void* gmem) {
    uint32_t s = (uint32_t)__cvta_generic_to_shared(smem);
    asm volatile("cp.async.cg.shared.global [%0], [%1], 16;\n" :: "r"(s), "l"(gmem));
}
DEV_INLINE void cp_commit() { asm volatile("cp.async.commit_group;\n"); }
template<int N> DEV_INLINE void cp_wait() { asm volatile("cp.async.wait_group %0;\n" :: "n"(N)); }
DEV_INLINE void wg_bar(int id) { asm volatile("bar.sync %0, 128;\n" :: "r"(id)); }

constexpr float L2E = 1.4426950408889634f;

// ---------------- kernel 1: weight prep ----------------
__global__ void prep_wt_kernel(const float* __restrict__ Wq,
                               const float* __restrict__ Wk,
                               const float* __restrict__ Wv) {
    int i = blockIdx.x * blockDim.x + threadIdx.x;
    if (i >= 3 * DH * DM) return;
    int which = i / (DH * DM);
    int r = i % (DH * DM);
    int dv = r / DM, k = r % DM;
    const float* W = (which == 0) ? Wq : (which == 1) ? Wk : Wv;
    float val = W[k * DH + dv];
    g_Wt[i] = __float2bfloat16(val);
    if (which == 2) g_WvtF[r] = val;   // fp32 transposed Wv for compute_c
}

// ---------------- projection GEMM body (pipelined) ----------------
template<int NT>
DEV_INLINE void proj_body(const float* __restrict__ X, int woff,
                          const float* __restrict__ bias0, const float* __restrict__ bias1,
                          float scale, int do_xsum, int blk, char* smraw) {
    float (*Xs)[128][68] = (float(*)[128][68])smraw;
    __nv_bfloat16 (*Ws)[NT * 8][72] =
        (__nv_bfloat16(*)[NT * 8][72])(smraw + 2 * 128 * 68 * 4);

    const int tid = threadIdx.x;
    const int w = tid >> 5, l = tid & 31, g = l >> 2, t4 = l & 3;
    const int rowbase = blk * 128;
    const __nv_bfloat16* Wt = g_Wt + woff;

    float acc[NT][4];
#pragma unroll
    for (int nt = 0; nt < NT; nt++)
#pragma unroll
        for (int j = 0; j < 4; j++) acc[nt][j] = 0.f;

    {
#pragma unroll
        for (int i = 0; i < 8; i++) {
            int e = tid + i * 256; int row = e >> 4, c4 = e & 15;
            cp_async16(&Xs[0][row][c4 * 4], X + (size_t)(rowbase + row) * DM + c4 * 4);
        }
#pragma unroll
        for (int i = 0; i < NT / 4; i++) {
            int e = tid + i * 256; int row = e >> 3, c8 = e & 7;
            cp_async16(&Ws[0][row][c8 * 8], Wt + (size_t)row * DM + c8 * 8);
        }
        cp_commit();
    }

    for (int kc = 0; kc < 12; kc++) {
        const int st = kc & 1;
        if (kc + 1 < 12) {
#pragma unroll
            for (int i = 0; i < 8; i++) {
                int e = tid + i * 256; int row = e >> 4, c4 = e & 15;
                cp_async16(&Xs[st ^ 1][row][c4 * 4],
                           X + (size_t)(rowbase + row) * DM + (kc + 1) * 64 + c4 * 4);
            }
#pragma unroll
            for (int i = 0; i < NT / 4; i++) {
                int e = tid + i * 256; int row = e >> 3, c8 = e & 7;
                cp_async16(&Ws[st ^ 1][row][c8 * 8],
                           Wt + (size_t)row * DM + (kc + 1) * 64 + c8 * 8);
            }
            cp_commit();
            cp_wait<1>();
        } else {
            cp_wait<0>();
        }
        __syncthreads();

        if (do_xsum) {
            const int q = tid >> 6, c = tid & 63;
            float s = 0.f;
#pragma unroll 8
            for (int r = 0; r < 32; r++) s += Xs[st][q * 32 + r][c];
            g_part4[((size_t)blk * 4 + q) * DM + kc * 64 + c] = s;
        }

        uint32_t a[4][4];
#pragma unroll
        for (int kt = 0; kt < 4; kt++) {
            int r0 = w * 16 + g, c0 = kt * 16 + 2 * t4;
            a[kt][0] = packbf2(Xs[st][r0][c0],         Xs[st][r0][c0 + 1]);
            a[kt][1] = packbf2(Xs[st][r0 + 8][c0],     Xs[st][r0 + 8][c0 + 1]);
            a[kt][2] = packbf2(Xs[st][r0][c0 + 8],     Xs[st][r0][c0 + 9]);
            a[kt][3] = packbf2(Xs[st][r0 + 8][c0 + 8], Xs[st][r0 + 8][c0 + 9]);
        }
#pragma unroll
        for (int nt = 0; nt < NT; nt++) {
#pragma unroll
            for (int kt = 0; kt < 4; kt++) {
                uint32_t bfr[2];
                int rn = nt * 8 + g, ck = kt * 16 + 2 * t4;
                bfr[0] = *(const uint32_t*)&Ws[st][rn][ck];
                bfr[1] = *(const uint32_t*)&Ws[st][rn][ck + 8];
                mma16816(acc[nt], a[kt], bfr);
            }
        }
        __syncthreads();
    }

    const int r0 = rowbase + w * 16 + g;
    if (NT == 8) {
#pragma unroll
        for (int nt = 0; nt < NT; nt++) {
            int c = nt * 8 + 2 * t4;
            float b0 = bias0[c], b1 = bias0[c + 1];
            *(uint32_t*)(g_Q + (size_t)r0 * DH + c) =
                packbf2((acc[nt][0] + b0) * scale, (acc[nt][1] + b1) * scale);
            *(uint32_t*)(g_Q + (size_t)(r0 + 8) * DH + c) =
                packbf2((acc[nt][2] + b0) * scale, (acc[nt][3] + b1) * scale);
        }
    } else {
#pragma unroll
        for (int nt = 0; nt < 8; nt++) {
            int c = nt * 8 + 2 * t4;
            float b0 = bias0[c], b1 = bias0[c + 1];
            *(uint32_t*)(g_K + (size_t)r0 * DH + c) =
                packbf2(acc[nt][0] + b0, acc[nt][1] + b1);
            *(uint32_t*)(g_K + (size_t)(r0 + 8) * DH + c) =
                packbf2(acc[nt][2] + b0, acc[nt][3] + b1);
        }
        __nv_bfloat16 (*Vsm)[72] = (__nv_bfloat16(*)[72])&Ws[0][0][0];
#pragma unroll
        for (int nt = 8; nt < 16; nt++) {
            int c = (nt - 8) * 8 + 2 * t4;
            float b0 = bias1[c], b1 = bias1[c + 1];
            *(uint32_t*)&Vsm[w * 16 + g][c]     = packbf2(acc[nt][0] + b0, acc[nt][1] + b1);
            *(uint32_t*)&Vsm[w * 16 + g + 8][c] = packbf2(acc[nt][2] + b0, acc[nt][3] + b1);
        }
        __syncthreads();
        const int b = rowbase >> 11, s0 = rowbase & 2047;
        const int d = tid >> 2, part = tid & 3;
#pragma unroll
        for (int jj = 0; jj < 4; jj++) {
            __nv_bfloat16 tmp[8];
#pragma unroll
            for (int m = 0; m < 8; m++) tmp[m] = Vsm[part * 32 + jj * 8 + m][d];
            *(uint4*)(g_Vt + ((size_t)(b * DH + d)) * S + s0 + part * 32 + jj * 8) =
                *(uint4*)tmp;
        }
    }
}

// fused: blocks 0..127 -> K|V on x2 ; blocks 128..255 -> Q on x1
__global__ __launch_bounds__(256) void proj_fused_kernel(
    const float* __restrict__ x1, const float* __restrict__ x2,
    const float* __restrict__ bq, const float* __restrict__ bk,
    const float* __restrict__ bv) {
    extern __shared__ char smraw[];
    if (blockIdx.x < 128)
        proj_body<16>(x2, DH * DM, bk, bv, 1.0f, 1, blockIdx.x, smraw);
    else
        proj_body<8>(x1, 0, bq, bq, 0.125f, 0, blockIdx.x - 128, smraw);
}

// ---------------- combine x2 partials (4 threads per output) ----------------
__global__ __launch_bounds__(256) void xsum_combine_kernel() {
    __shared__ float red[4][64];
    const int sub = threadIdx.x >> 6, ol = threadIdx.x & 63;
    const int o = blockIdx.x * 64 + ol;           // 0..6143 (DM*BB)
    const int b = o / DM, c = o % DM;
    float a = 0.f;
#pragma unroll
    for (int i = 0; i < 16; i++)
        a += g_part4[(size_t)(b * 64 + sub * 16 + i) * DM + c];
    red[sub][ol] = a;
    __syncthreads();
    if (sub == 0)
        g_xsum[o] = red[0][ol] + red[1][ol] + red[2][ol] + red[3][ol];
}

// ---------------- c = xsum @ Wv + S*bv ----------------
__global__ void compute_c_kernel(const float* __restrict__ bv) {
    int idx = blockIdx.x * 8 + (threadIdx.x >> 5);
    int lane = threadIdx.x & 31;
    int b = idx >> 6, d = idx & 63;
    const float* xs = g_xsum + b * DM;
    const float* wt = g_WvtF + (size_t)d * DM;
    float acc = 0.f;
#pragma unroll
    for (int i = 0; i < DM / 32; i++) {
        int j = lane + i * 32;
        acc += xs[j] * wt[j];
    }
#pragma unroll
    for (int off = 16; off; off >>= 1) acc += __shfl_xor_sync(0xffffffffu, acc, off);
    if (lane == 0) g_c[idx] = acc + 2048.0f * bv[d];
}

// ---------------- flash attention (split-K warpgroups) + LN ----------------
// smem: Kb4[4][64][72] | Vb4[4][64][72] | cs[192]
constexpr int SMATT = 4 * 64 * 72 * 2 * 2 + 192 * 4;   // 73728 + 768

__global__ __launch_bounds__(256) void attn_kernel(const float* __restrict__ gamma,
                                                   const float* __restrict__ beta,
                                                   float* __restrict__ out) {
    extern __shared__ char sm[];
    __nv_bfloat16 (*Kb4)[64][72] = (__nv_bfloat16(*)[64][72])sm;
    __nv_bfloat16 (*Vb4)[64][72] = (__nv_bfloat16(*)[64][72])(sm + 36864);
    float* cs = (float*)(sm + 73728);

    const int qt = blockIdx.x, b = blockIdx.y;
    const int tid = threadIdx.x;
    const int w = tid >> 5, l = tid & 31, g = l >> 2, t4 = l & 3;
    const int wg = w >> 2, ww = w & 3;
    const int wt128 = tid & 127;

    // Q staging (overlaps Kb4[0..1] region; consumed before K prefetch)
    __nv_bfloat16 (*Qs)[72] = (__nv_bfloat16(*)[72])sm;
    const __nv_bfloat16* Qp = g_Q + ((size_t)b * S + qt * 128) * DH;
#pragma unroll
    for (int i = 0; i < 4; i++) {
        int e = tid + i * 256; int row = e >> 3, c8 = e & 7;
        cp_async16(&Qs[row][c8 * 8], Qp + (size_t)row * DH + c8 * 8);
    }
    cp_commit();
    if (tid < 64)        cs[tid] = g_c[b * 64 + tid];
    else if (tid < 128)  cs[tid] = gamma[tid - 64];
    else if (tid < 192)  cs[tid] = beta[tid - 128];
    cp_wait<0>();
    __syncthreads();

    uint32_t aq[2][4][4];
#pragma unroll
    for (int mt = 0; mt < 2; mt++) {
        int r0 = ww * 32 + mt * 16 + g;
#pragma unroll
        for (int kt = 0; kt < 4; kt++) {
            int c0 = kt * 16 + 2 * t4;
            aq[mt][kt][0] = *(const uint32_t*)&Qs[r0][c0];
            aq[mt][kt][1] = *(const uint32_t*)&Qs[r0 + 8][c0];
            aq[mt][kt][2] = *(const uint32_t*)&Qs[r0][c0 + 8];
            aq[mt][kt][3] = *(const uint32_t*)&Qs[r0 + 8][c0 + 8];
        }
    }
    __syncthreads();

    const __nv_bfloat16* Kbase = g_K  + (size_t)b * S * DH;
    const __nv_bfloat16* Vtb   = g_Vt + (size_t)b * DH * S;

    // prologue: tile tau = wg
    {
        int tau = wg;
#pragma unroll
        for (int i = 0; i < 4; i++) {
            int e = wt128 + i * 128; int row = e >> 3, c8 = e & 7;
            cp_async16(&Kb4[wg * 2][row][c8 * 8],
                       Kbase + (size_t)(tau * 64 + row) * DH + c8 * 8);
        }
#pragma unroll
        for (int i = 0; i < 4; i++) {
            int e = wt128 + i * 128; int row = e >> 3, c8 = e & 7;
            cp_async16(&Vb4[wg * 2][row][c8 * 8],
                       Vtb + (size_t)row * S + tau * 64 + c8 * 8);
        }
        cp_commit();
    }

    float o[2][8][4];
#pragma unroll
    for (int mt = 0; mt < 2; mt++)
#pragma unroll
        for (int nv = 0; nv < 8; nv++)
#pragma unroll
            for (int j = 0; j < 4; j++) o[mt][nv][j] = 0.f;
    float ls[2][2] = {{0.f, 0.f}, {0.f, 0.f}};

    for (int t = 0; t < 16; t++) {
        const int st = t & 1, bi = wg * 2 + st;
        if (t + 1 < 16) {
            int tau = 2 * (t + 1) + wg, b2 = wg * 2 + (st ^ 1);
#pragma unroll
            for (int i = 0; i < 4; i++) {
                int e = wt128 + i * 128; int row = e >> 3, c8 = e & 7;
                cp_async16(&Kb4[b2][row][c8 * 8],
                           Kbase + (size_t)(tau * 64 + row) * DH + c8 * 8);
            }
#pragma unroll
            for (int i = 0; i < 4; i++) {
                int e = wt128 + i * 128; int row = e >> 3, c8 = e & 7;
                cp_async16(&Vb4[b2][row][c8 * 8],
                           Vtb + (size_t)row * S + tau * 64 + c8 * 8);
            }
            cp_commit();
            cp_wait<1>();
        } else {
            cp_wait<0>();
        }
        wg_bar(wg + 1);

        const __nv_bfloat16 (*Kst)[72] = Kb4[bi];
        const __nv_bfloat16 (*Vst)[72] = Vb4[bi];

        uint32_t pa[2][4][4];
#pragma unroll
        for (int nt = 0; nt < 8; nt++) {
            uint32_t kf[4][2];
            const int rn = nt * 8 + g;
#pragma unroll
            for (int kt = 0; kt < 4; kt++) {
                int ck = kt * 16 + 2 * t4;
                kf[kt][0] = *(const uint32_t*)&Kst[rn][ck];
                kf[kt][1] = *(const uint32_t*)&Kst[rn][ck + 8];
            }
#pragma unroll
            for (int mt = 0; mt < 2; mt++) {
                float sc4[4] = {0.f, 0.f, 0.f, 0.f};
#pragma unroll
                for (int kt = 0; kt < 4; kt++) mma16816(sc4, aq[mt][kt], kf[kt]);
                float p0 = ex2f(sc4[0] * L2E);
                float p1 = ex2f(sc4[1] * L2E);
                float p2 = ex2f(sc4[2] * L2E);
                float p3 = ex2f(sc4[3] * L2E);
                ls[mt][0] += p0 + p1;
                ls[mt][1] += p2 + p3;
                pa[mt][nt >> 1][(nt & 1) * 2 + 0] = packbf2(p0, p1);
                pa[mt][nt >> 1][(nt & 1) * 2 + 1] = packbf2(p2, p3);
            }
        }
#pragma unroll
        for (int nv = 0; nv < 8; nv++) {
            uint32_t vf[4][2];
            const int rd = nv * 8 + g;
#pragma unroll
            for (int k2 = 0; k2 < 4; k2++) {
                int cc = k2 * 16 + 2 * t4;
                vf[k2][0] = *(const uint32_t*)&Vst[rd][cc];
                vf[k2][1] = *(const uint32_t*)&Vst[rd][cc + 8];
            }
#pragma unroll
            for (int mt = 0; mt < 2; mt++)
#pragma unroll
                for (int k2 = 0; k2 < 4; k2++)
                    mma16816(o[mt][nv], pa[mt][k2], vf[k2]);
        }
        wg_bar(wg + 1);
    }

    // cross-WG combine (Kb4 region reused as fp32 exchange)
    __syncthreads();
    float* ex = (float*)sm;                     // 4 warps * 2176 floats
    if (wg == 1) {
        float* dst = ex + ww * 2176;
#pragma unroll
        for (int mt = 0; mt < 2; mt++)
#pragma unroll
            for (int nv = 0; nv < 8; nv++)
#pragma unroll
                for (int j = 0; j < 4; j++)
                    dst[((mt * 8 + nv) * 4 + j) * 32 + l] = o[mt][nv][j];
#pragma unroll
        for (int mt = 0; mt < 2; mt++)
#pragma unroll
            for (int h = 0; h < 2; h++)
                dst[2048 + (mt * 2 + h) * 32 + l] = ls[mt][h];
    }
    __syncthreads();
    if (wg == 0) {
        const float* src = ex + ww * 2176;
#pragma unroll
        for (int mt = 0; mt < 2; mt++)
#pragma unroll
            for (int nv = 0; nv < 8; nv++)
#pragma unroll
                for (int j = 0; j < 4; j++)
                    o[mt][nv][j] += src[((mt * 8 + nv) * 4 + j) * 32 + l];
#pragma unroll
        for (int mt = 0; mt < 2; mt++)
#pragma unroll
            for (int h = 0; h < 2; h++) {
                float v = ls[mt][h] + src[2048 + (mt * 2 + h) * 32 + l];
                v += __shfl_xor_sync(0xffffffffu, v, 1);
                v += __shfl_xor_sync(0xffffffffu, v, 2);
                ls[mt][h] = v;
            }

        const float* gs = cs + 64;
        const float* bs = cs + 128;
        const float isc = 1.f / 2047.f;
#pragma unroll
        for (int mt = 0; mt < 2; mt++) {
            const float inv0 = 1.f / ls[mt][0];
            const float inv1 = 1.f / ls[mt][1];
            float s1a = 0.f, s2a = 0.f, s1b = 0.f, s2b = 0.f;
#pragma unroll
            for (int nv = 0; nv < 8; nv++) {
                int c = nv * 8 + 2 * t4;
                float cc0 = cs[c], cc1 = cs[c + 1];
                float x0 = (cc0 - o[mt][nv][0] * inv0) * isc;
                float x1 = (cc1 - o[mt][nv][1] * inv0) * isc;
                float y0 = (cc0 - o[mt][nv][2] * inv1) * isc;
                float y1 = (cc1 - o[mt][nv][3] * inv1) * isc;
                s1a += x0 + x1; s2a += x0 * x0 + x1 * x1;
                s1b += y0 + y1; s2b += y0 * y0 + y1 * y1;
                o[mt][nv][0] = x0; o[mt][nv][1] = x1;
                o[mt][nv][2] = y0; o[mt][nv][3] = y1;
            }
#pragma unroll
            for (int off = 1; off <= 2; off <<= 1) {
                s1a += __shfl_xor_sync(0xffffffffu, s1a, off);
                s2a += __shfl_xor_sync(0xffffffffu, s2a, off);
                s1b += __shfl_xor_sync(0xffffffffu, s1b, off);
                s2b += __shfl_xor_sync(0xffffffffu, s2b, off);
            }
            float mu0 = s1a * (1.f / 64.f), var0 = s2a * (1.f / 64.f) - mu0 * mu0;
            float mu1 = s1b * (1.f / 64.f), var1 = s2b * (1.f / 64.f) - mu1 * mu1;
            float r0f = rsqrtf(var0 + 1e-5f);
            float r1f = rsqrtf(var1 + 1e-5f);

            const int row0 = b * S + qt * 128 + ww * 32 + mt * 16 + g;
#pragma unroll
            for (int nv = 0; nv < 8; nv++) {
                int c = nv * 8 + 2 * t4;
                float ga0 = gs[c], ga1 = gs[c + 1], be0 = bs[c], be1 = bs[c + 1];
                *(float2*)(out + (size_t)row0 * DH + c) =
                    make_float2((o[mt][nv][0] - mu0) * r0f * ga0 + be0,
                                (o[mt][nv][1] - mu0) * r0f * ga1 + be1);
                *(float2*)(out + (size_t)(row0 + 8) * DH + c) =
                    make_float2((o[mt][nv][2] - mu1) * r1f * ga0 + be0,
                                (o[mt][nv][3] - mu1) * r1f * ga1 + be1);
            }
        }
    }
}

// ---------------- launch ----------------
extern "C" void kernel_launch(void* const* d_in, const int* in_sizes, int n_in,
                              void* d_out, int out_size) {
    const float* x1 = (const float*)d_in[0];
    const float* x2 = (const float*)d_in[1];
    const float* Wq = (const float*)d_in[2];
    const float* bq = (const float*)d_in[3];
    const float* Wk = (const float*)d_in[4];
    const float* bk = (const float*)d_in[5];
    const float* Wv = (const float*)d_in[6];
    const float* bv = (const float*)d_in[7];
    const float* gamma = (const float*)d_in[8];
    const float* beta  = (const float*)d_in[9];
    float* out = (float*)d_out;

    const int SM16 = 2 * 128 * 68 * 4 + 2 * 128 * 72 * 2;   // 106496
    cudaFuncSetAttribute(proj_fused_kernel, cudaFuncAttributeMaxDynamicSharedMemorySize, SM16);
    cudaFuncSetAttribute(attn_kernel, cudaFuncAttributeMaxDynamicSharedMemorySize, SMATT);

    prep_wt_kernel<<<(3 * DH * DM + 255) / 256, 256>>>(Wq, Wk, Wv);
    proj_fused_kernel<<<256, 256, SM16>>>(x1, x2, bq, bk, bv);
    xsum_combine_kernel<<<96, 256>>>();
    compute_c_kernel<<<64, 256>>>(bv);
    attn_kernel<<<dim3(16, BB), 256, SMATT>>>(gamma, beta, out);
}